// round 5
// baseline (speedup 1.0000x reference)
#include <cuda_runtime.h>
#include <cuda_bf16.h>
#include <cstdint>
#include <cstddef>

#define BB 8
#define SS 4096
#define DD 256
#define CC 128
#define NCHUNK 32
#define NBC (BB * NCHUNK)   // 256 chunks total

// Scratch
__device__ float         g_S [(size_t)NBC * DD * DD];   // per-chunk S, [bc][i][j] (67 MB)
__device__ __nv_bfloat16 g_Hh[(size_t)NBC * DD * DD];   // incoming state hi (33.5 MB)
__device__ __nv_bfloat16 g_Hl[(size_t)NBC * DD * DD];   // incoming state lo (33.5 MB)
__device__ float g_Lg[NBC * CC];
__device__ float g_Gamma[NBC];

// ---------------------------------------------------------------------------
// Helpers
// ---------------------------------------------------------------------------
__device__ __forceinline__ uint32_t smem_u32(const void* p) {
    uint32_t a;
    asm("{ .reg .u64 t; cvta.to.shared.u64 t, %1; cvt.u32.u64 %0, t; }"
        : "=r"(a) : "l"(p));
    return a;
}

__device__ __forceinline__ void mma16816(float c[4], const uint32_t a[4],
                                         const uint32_t b[2]) {
    asm volatile(
        "mma.sync.aligned.m16n8k16.row.col.f32.bf16.bf16.f32 "
        "{%0,%1,%2,%3}, {%4,%5,%6,%7}, {%8,%9}, {%0,%1,%2,%3};"
        : "+f"(c[0]), "+f"(c[1]), "+f"(c[2]), "+f"(c[3])
        : "r"(a[0]), "r"(a[1]), "r"(a[2]), "r"(a[3]), "r"(b[0]), "r"(b[1]));
}

__device__ __forceinline__ void ldmx4(uint32_t r[4], uint32_t a) {
    asm volatile("ldmatrix.sync.aligned.m8n8.x4.shared.b16 {%0,%1,%2,%3}, [%4];"
                 : "=r"(r[0]), "=r"(r[1]), "=r"(r[2]), "=r"(r[3]) : "r"(a));
}
__device__ __forceinline__ void ldmx4t(uint32_t r[4], uint32_t a) {
    asm volatile("ldmatrix.sync.aligned.m8n8.x4.trans.shared.b16 {%0,%1,%2,%3}, [%4];"
                 : "=r"(r[0]), "=r"(r[1]), "=r"(r[2]), "=r"(r[3]) : "r"(a));
}

__device__ __forceinline__ void split4(float4 v, uint2& hi, uint2& lo) {
    float x[4] = { v.x, v.y, v.z, v.w };
    uint32_t h[4], l[4];
    #pragma unroll
    for (int u = 0; u < 4; u++) {
        __nv_bfloat16 hb = __float2bfloat16(x[u]);
        float rres = x[u] - __bfloat162float(hb);
        __nv_bfloat16 lb = __float2bfloat16(rres);
        h[u] = (uint32_t)__bfloat16_as_ushort(hb);
        l[u] = (uint32_t)__bfloat16_as_ushort(lb);
    }
    hi.x = h[0] | (h[1] << 16); hi.y = h[2] | (h[3] << 16);
    lo.x = l[0] | (l[1] << 16); lo.y = l[2] | (l[3] << 16);
}

__device__ __forceinline__ uint32_t pack_bf16x2(float x, float y) {
    __nv_bfloat16 a = __float2bfloat16(x), b = __float2bfloat16(y);
    return (uint32_t)__bfloat16_as_ushort(a) |
           ((uint32_t)__bfloat16_as_ushort(b) << 16);
}

// smem strides (bf16 elems), ≡ 8 (mod 16): conflict-free ldmatrix rows
#define SP 72    // 64-wide panels
#define SV 136   // 128-wide tiles
#define SA 136   // A_att rows (128 wide)

// ---------------------------------------------------------------------------
// Kernel A: S quadrant [128 i][128 j]; grid (NBC, 4), 512 threads.
//   S[i][j] = sum_{tau<128} (w_tau K[tau][i]) V[tau][j]
// ---------------------------------------------------------------------------
#define S_WV   0
#define S_LG   512
#define S_KH   1024
#define S_KL   (S_KH + 128 * SV * 2)
#define S_VH   (S_KL + 128 * SV * 2)
#define S_VL   (S_VH + 128 * SV * 2)
#define S_SMEM (S_VL + 128 * SV * 2)   // 140288

__global__ __launch_bounds__(512) void dr_state(
    const float* __restrict__ K, const float* __restrict__ V,
    const float* __restrict__ beta)
{
    extern __shared__ char sm[];
    float* wv  = (float*)(sm + S_WV);
    float* sLg = (float*)(sm + S_LG);
    const int bc = blockIdx.x;
    const int qi = blockIdx.y >> 1, qj = blockIdx.y & 1;
    const int b = bc >> 5, c = bc & 31;
    const int tid = threadIdx.x, wid = tid >> 5, lane = tid & 31;

    if (tid < CC) sLg[tid] = __logf(fmaxf(beta[b * SS + c * CC + tid], 1e-30f));
    __syncthreads();
    if (tid == 0) {
        float s = 0.f;
        #pragma unroll
        for (int u = 0; u < CC; u++) { s += sLg[u]; sLg[u] = s; }
    }
    __syncthreads();
    const float LgEnd = sLg[CC - 1];
    if (tid < CC) {
        wv[tid] = __expf(LgEnd - sLg[tid]);
        if (blockIdx.y == 0) g_Lg[bc * CC + tid] = sLg[tid];
    }
    if (blockIdx.y == 0 && tid == 0) g_Gamma[bc] = __expf(LgEnd);
    __syncthreads();

    __nv_bfloat16* KH = (__nv_bfloat16*)(sm + S_KH);
    __nv_bfloat16* KL = (__nv_bfloat16*)(sm + S_KL);
    __nv_bfloat16* VH = (__nv_bfloat16*)(sm + S_VH);
    __nv_bfloat16* VL = (__nv_bfloat16*)(sm + S_VL);

    const float* Kg = K + ((size_t)b * SS + (size_t)c * CC) * DD + qi * 128;
    const float* Vg = V + ((size_t)b * SS + (size_t)c * CC) * DD + qj * 128;

    #pragma unroll
    for (int it = 0; it < 8; it++) {
        int idx = it * 512 + tid;                 // 0..4095
        int tau = idx >> 5, c4 = (idx & 31) << 2;
        float4 kq = *(const float4*)(Kg + (size_t)tau * DD + c4);
        float wt = wv[tau];
        float4 sc = { kq.x * wt, kq.y * wt, kq.z * wt, kq.w * wt };
        uint2 h, l; split4(sc, h, l);
        *(uint2*)(KH + tau * SV + c4) = h;
        *(uint2*)(KL + tau * SV + c4) = l;
        float4 vq = *(const float4*)(Vg + (size_t)tau * DD + c4);
        split4(vq, h, l);
        *(uint2*)(VH + tau * SV + c4) = h;
        *(uint2*)(VL + tau * SV + c4) = l;
    }
    __syncthreads();

    const int mat = lane >> 3, r = lane & 7, g = lane >> 2, q = lane & 3;
    // trans ldmatrix offsets (data stored [k][m] / [k][n], stride SV)
    const uint32_t offAt = (uint32_t)((((mat >> 1) * 8 + r) * (SV * 2)) + (mat & 1) * 16);
    const uint32_t offBt = (uint32_t)((((mat & 1) * 8 + r) * (SV * 2)) + (mat >> 1) * 16);
    const uint32_t khb = smem_u32(sm + S_KH), klb = smem_u32(sm + S_KL);
    const uint32_t vhb = smem_u32(sm + S_VH), vlb = smem_u32(sm + S_VL);

    const int i0w = (wid >> 2) * 32, j0w = (wid & 3) * 32;

    float acc[2][4][4];
    #pragma unroll
    for (int mt = 0; mt < 2; mt++)
        #pragma unroll
        for (int nt = 0; nt < 4; nt++)
            #pragma unroll
            for (int u = 0; u < 4; u++) acc[mt][nt][u] = 0.f;

    #pragma unroll
    for (int pass = 0; pass < 3; pass++) {
        uint32_t ab = (pass == 2) ? klb : khb;
        uint32_t bb = (pass == 1) ? vlb : vhb;
        #pragma unroll
        for (int k0 = 0; k0 < 128; k0 += 16) {
            uint32_t af[2][4], bfm[2][4];
            #pragma unroll
            for (int mt = 0; mt < 2; mt++)
                ldmx4t(af[mt], ab + (uint32_t)(k0 * (SV * 2) + (i0w + mt * 16) * 2) + offAt);
            #pragma unroll
            for (int ng = 0; ng < 2; ng++)
                ldmx4t(bfm[ng], bb + (uint32_t)(k0 * (SV * 2) + (j0w + ng * 16) * 2) + offBt);
            #pragma unroll
            for (int mt = 0; mt < 2; mt++)
                #pragma unroll
                for (int nt = 0; nt < 4; nt++)
                    mma16816(acc[mt][nt], af[mt], &bfm[nt >> 1][(nt & 1) * 2]);
        }
    }

    float* Sdst = g_S + (size_t)bc * 65536 + (size_t)(qi * 128) * 256 + qj * 128;
    #pragma unroll
    for (int mt = 0; mt < 2; mt++)
        #pragma unroll
        for (int nt = 0; nt < 4; nt++) {
            int i = i0w + mt * 16 + g;
            int j = j0w + nt * 8 + 2 * q;
            float2 v0 = { acc[mt][nt][0], acc[mt][nt][1] };
            float2 v1 = { acc[mt][nt][2], acc[mt][nt][3] };
            *(float2*)(Sdst + (size_t)i * 256 + j) = v0;
            *(float2*)(Sdst + (size_t)(i + 8) * 256 + j) = v1;
        }
}

// ---------------------------------------------------------------------------
// Kernel B: cross-chunk scan (32 steps), float4 per thread.
// ---------------------------------------------------------------------------
__global__ __launch_bounds__(256) void dr_scan()
{
    const int b = blockIdx.y;
    const int tid = threadIdx.x;
    const size_t e4 = ((size_t)blockIdx.x * 256 + tid) * 4;
    __shared__ float gam[NCHUNK];
    if (tid < NCHUNK) gam[tid] = g_Gamma[b * NCHUNK + tid];
    __syncthreads();

    float4 h = { 0.f, 0.f, 0.f, 0.f };
    const size_t base = (size_t)b * NCHUNK * 65536 + e4;
    #pragma unroll 4
    for (int c = 0; c < NCHUNK; c++) {
        const size_t off = base + (size_t)c * 65536;
        float4 s = *(const float4*)(g_S + off);
        __nv_bfloat16 hx = __float2bfloat16(h.x), hy = __float2bfloat16(h.y);
        __nv_bfloat16 hz = __float2bfloat16(h.z), hw = __float2bfloat16(h.w);
        uint2 hh = { (uint32_t)__bfloat16_as_ushort(hx) |
                     ((uint32_t)__bfloat16_as_ushort(hy) << 16),
                     (uint32_t)__bfloat16_as_ushort(hz) |
                     ((uint32_t)__bfloat16_as_ushort(hw) << 16) };
        uint2 ll = { pack_bf16x2(h.x - __bfloat162float(hx), h.y - __bfloat162float(hy)),
                     pack_bf16x2(h.z - __bfloat162float(hz), h.w - __bfloat162float(hw)) };
        *(uint2*)(g_Hh + off) = hh;
        *(uint2*)(g_Hl + off) = ll;
        float gc = gam[c];
        h.x = gc * h.x + s.x; h.y = gc * h.y + s.y;
        h.z = gc * h.z + s.z; h.w = gc * h.w + s.w;
    }
}

// ---------------------------------------------------------------------------
// Kernel C: fused output per (bc, jh): O[:, jh*128..] (128 x 128) =
//   (gQ) @ H[:, jh] + mask(QK^T) @ V[:, jh]
// 512 threads; paneled phases.
// ---------------------------------------------------------------------------
#define O_P0   1024
#define O_P1   (O_P0 + 128 * SV * 2)   // 35840
#define O_P2   (O_P1 + 128 * SV * 2)   // 70656
#define O_P3   (O_P2 + 128 * SV * 2)   // 105472
#define O_ASH  (O_P3 + 128 * SV * 2)   // 140288
#define O_ASL  (O_ASH + 128 * SA * 2)  // 175104
#define O_SMEM (O_ASL + 128 * SA * 2)  // 209920

__global__ __launch_bounds__(512) void dr_out(
    const float* __restrict__ Q, const float* __restrict__ K,
    const float* __restrict__ V, float* __restrict__ O)
{
    extern __shared__ char sm[];
    float* sLg = (float*)(sm + 0);
    float* sg  = (float*)(sm + 512);
    const int bc = blockIdx.x, jh = blockIdx.y;
    const int b = bc >> 5, c = bc & 31;
    const int tid = threadIdx.x, wid = tid >> 5, lane = tid & 31;

    if (tid < CC) {
        float lg = g_Lg[bc * CC + tid];
        sLg[tid] = lg;
        sg[tid]  = __expf(lg);
    }
    __syncthreads();

    const size_t chbase = ((size_t)b * SS + (size_t)c * CC) * DD;
    const int mat = lane >> 3, r = lane & 7, g = lane >> 2, q = lane & 3;
    const uint32_t offA_SP  = (uint32_t)((((mat & 1) * 8 + r) * (SP * 2)) + (mat >> 1) * 16);
    const uint32_t offB4_SP = (uint32_t)((((lane >> 4) * 8 + (lane & 7)) * (SP * 2)) +
                                         ((lane >> 3) & 1) * 16);
    const uint32_t offA_SA  = (uint32_t)((((mat & 1) * 8 + r) * (SA * 2)) + (mat >> 1) * 16);
    const uint32_t offNT_SV = (uint32_t)((((mat & 1) * 8 + r) * (SV * 2)) + (mat >> 1) * 16);

    const uint32_t p0 = smem_u32(sm + O_P0), p1 = smem_u32(sm + O_P1);
    const uint32_t p2 = smem_u32(sm + O_P2), p3 = smem_u32(sm + O_P3);
    const uint32_t ash = smem_u32(sm + O_ASH), asl = smem_u32(sm + O_ASL);

    // ---- Phase 1: A = QK^T over 4 d-panels of 64 ----
    const int i0a = (wid >> 2) * 32, t0 = (wid & 3) * 32;
    float accA[2][4][4];
    #pragma unroll
    for (int mt = 0; mt < 2; mt++)
        #pragma unroll
        for (int nt = 0; nt < 4; nt++)
            #pragma unroll
            for (int u = 0; u < 4; u++) accA[mt][nt][u] = 0.f;

    __nv_bfloat16* QpH = (__nv_bfloat16*)(sm + O_P0);
    __nv_bfloat16* QpL = (__nv_bfloat16*)(sm + O_P1);
    __nv_bfloat16* KpH = (__nv_bfloat16*)(sm + O_P2);
    __nv_bfloat16* KpL = (__nv_bfloat16*)(sm + O_P3);

    for (int dp = 0; dp < 4; dp++) {
        if (dp) __syncthreads();
        #pragma unroll
        for (int it = 0; it < 4; it++) {
            int idx = it * 512 + tid;             // 0..2047
            int row = idx >> 4, c4 = (idx & 15) << 2;
            float4 qv = *(const float4*)(Q + chbase + (size_t)row * DD + dp * 64 + c4);
            uint2 h, l; split4(qv, h, l);
            *(uint2*)(QpH + row * SP + c4) = h;
            *(uint2*)(QpL + row * SP + c4) = l;
            float4 kv = *(const float4*)(K + chbase + (size_t)row * DD + dp * 64 + c4);
            split4(kv, h, l);
            *(uint2*)(KpH + row * SP + c4) = h;
            *(uint2*)(KpL + row * SP + c4) = l;
        }
        __syncthreads();
        #pragma unroll
        for (int pass = 0; pass < 3; pass++) {
            uint32_t ab = (pass == 2) ? p1 : p0;
            uint32_t bb = (pass == 1) ? p3 : p2;
            #pragma unroll
            for (int k0 = 0; k0 < 64; k0 += 16) {
                uint32_t af[2][4], bf2[2][4];
                #pragma unroll
                for (int mt = 0; mt < 2; mt++)
                    ldmx4(af[mt], ab + (uint32_t)((i0a + mt * 16) * (SP * 2) + k0 * 2) + offA_SP);
                #pragma unroll
                for (int ng = 0; ng < 2; ng++)
                    ldmx4(bf2[ng], bb + (uint32_t)((t0 + ng * 16) * (SP * 2) + k0 * 2) + offB4_SP);
                #pragma unroll
                for (int mt = 0; mt < 2; mt++)
                    #pragma unroll
                    for (int nt = 0; nt < 4; nt++)
                        mma16816(accA[mt][nt], af[mt], &bf2[nt >> 1][(nt & 1) * 2]);
            }
        }
    }

    // ---- Phase 2: mask + decay -> ASH/ASL ----
    __nv_bfloat16* ASH = (__nv_bfloat16*)(sm + O_ASH);
    __nv_bfloat16* ASL = (__nv_bfloat16*)(sm + O_ASL);
    #pragma unroll
    for (int mt = 0; mt < 2; mt++)
        #pragma unroll
        for (int nt = 0; nt < 4; nt++) {
            int ia = i0a + mt * 16 + g, ib = ia + 8;
            int t = t0 + nt * 8 + 2 * q;
            float la = sLg[ia], lb = sLg[ib], l0 = sLg[t], l1 = sLg[t + 1];
            float f00 = (t     <= ia) ? __expf(la - l0) : 0.f;
            float f01 = (t + 1 <= ia) ? __expf(la - l1) : 0.f;
            float f10 = (t     <= ib) ? __expf(lb - l0) : 0.f;
            float f11 = (t + 1 <= ib) ? __expf(lb - l1) : 0.f;
            float a0 = accA[mt][nt][0] * f00, a1 = accA[mt][nt][1] * f01;
            float a2 = accA[mt][nt][2] * f10, a3 = accA[mt][nt][3] * f11;
            __nv_bfloat16 h0 = __float2bfloat16(a0), h1 = __float2bfloat16(a1);
            __nv_bfloat16 h2 = __float2bfloat16(a2), h3 = __float2bfloat16(a3);
            *(uint32_t*)(ASH + ia * SA + t) =
                (uint32_t)__bfloat16_as_ushort(h0) | ((uint32_t)__bfloat16_as_ushort(h1) << 16);
            *(uint32_t*)(ASH + ib * SA + t) =
                (uint32_t)__bfloat16_as_ushort(h2) | ((uint32_t)__bfloat16_as_ushort(h3) << 16);
            *(uint32_t*)(ASL + ia * SA + t) =
                pack_bf16x2(a0 - __bfloat162float(h0), a1 - __bfloat162float(h1));
            *(uint32_t*)(ASL + ib * SA + t) =
                pack_bf16x2(a2 - __bfloat162float(h2), a3 - __bfloat162float(h3));
        }
    __syncthreads();

    // ---- Phase 3: O = A @ V(jh) ----
    __nv_bfloat16* VH = (__nv_bfloat16*)(sm + O_P0);
    __nv_bfloat16* VL = (__nv_bfloat16*)(sm + O_P1);
    #pragma unroll
    for (int it = 0; it < 8; it++) {
        int idx = it * 512 + tid;                 // 0..4095
        int row = idx >> 5, c4 = (idx & 31) << 2;
        float4 vv = *(const float4*)(V + chbase + (size_t)row * DD + jh * 128 + c4);
        uint2 h, l; split4(vv, h, l);
        *(uint2*)(VH + row * SV + c4) = h;
        *(uint2*)(VL + row * SV + c4) = l;
    }
    __syncthreads();

    const int i0o = (wid >> 2) * 32, j0o = (wid & 3) * 32;
    float accO[2][4][4];
    #pragma unroll
    for (int mt = 0; mt < 2; mt++)
        #pragma unroll
        for (int nt = 0; nt < 4; nt++)
            #pragma unroll
            for (int u = 0; u < 4; u++) accO[mt][nt][u] = 0.f;

    #pragma unroll
    for (int pass = 0; pass < 3; pass++) {
        uint32_t ab = (pass == 2) ? asl : ash;
        uint32_t bb = (pass == 1) ? p1 : p0;
        #pragma unroll
        for (int k0 = 0; k0 < 128; k0 += 16) {
            uint32_t af[2][4], bfm[2][4];
            #pragma unroll
            for (int mt = 0; mt < 2; mt++)
                ldmx4(af[mt], ab + (uint32_t)((i0o + mt * 16) * (SA * 2) + k0 * 2) + offA_SA);
            #pragma unroll
            for (int ng = 0; ng < 2; ng++)
                ldmx4t(bfm[ng], bb + (uint32_t)(k0 * (SV * 2) + (j0o + ng * 16) * 2) + offNT_SV);
            #pragma unroll
            for (int mt = 0; mt < 2; mt++)
                #pragma unroll
                for (int nt = 0; nt < 4; nt++)
                    mma16816(accO[mt][nt], af[mt], &bfm[nt >> 1][(nt & 1) * 2]);
        }
    }
    __syncthreads();

    // ---- Phase 4: O += (gQ) @ H(jh), 2 d-panels of 128 ----
    __nv_bfloat16* GQH = (__nv_bfloat16*)(sm + O_P0);
    __nv_bfloat16* GQL = (__nv_bfloat16*)(sm + O_P1);
    __nv_bfloat16* HpH = (__nv_bfloat16*)(sm + O_P2);
    __nv_bfloat16* HpL = (__nv_bfloat16*)(sm + O_P3);
    const __nv_bfloat16* HgH = g_Hh + (size_t)bc * 65536 + jh * 128;
    const __nv_bfloat16* HgL = g_Hl + (size_t)bc * 65536 + jh * 128;

    for (int hp = 0; hp < 2; hp++) {
        if (hp) __syncthreads();
        #pragma unroll
        for (int it = 0; it < 8; it++) {
            int idx = it * 512 + tid;             // 0..4095
            int row = idx >> 5, c4 = (idx & 31) << 2;
            float4 qv = *(const float4*)(Q + chbase + (size_t)row * DD + hp * 128 + c4);
            float gi = sg[row];
            float4 sc = { qv.x * gi, qv.y * gi, qv.z * gi, qv.w * gi };
            uint2 h, l; split4(sc, h, l);
            *(uint2*)(GQH + row * SV + c4) = h;
            *(uint2*)(GQL + row * SV + c4) = l;
        }
        #pragma unroll
        for (int it = 0; it < 4; it++) {
            int idx = it * 512 + tid;             // 0..2047
            int row = idx >> 4, u = (idx & 15) * 8;
            *(uint4*)(HpH + row * SV + u) =
                *(const uint4*)(HgH + (size_t)(hp * 128 + row) * 256 + u);
            *(uint4*)(HpL + row * SV + u) =
                *(const uint4*)(HgL + (size_t)(hp * 128 + row) * 256 + u);
        }
        __syncthreads();
        #pragma unroll
        for (int pass = 0; pass < 3; pass++) {
            uint32_t ab = (pass == 2) ? p1 : p0;
            uint32_t bb = (pass == 1) ? p3 : p2;
            #pragma unroll
            for (int k0 = 0; k0 < 128; k0 += 16) {
                uint32_t af[2][4], bfm[2][4];
                #pragma unroll
                for (int mt = 0; mt < 2; mt++)
                    ldmx4(af[mt], ab + (uint32_t)((i0o + mt * 16) * (SV * 2) + k0 * 2) + offNT_SV);
                #pragma unroll
                for (int ng = 0; ng < 2; ng++)
                    ldmx4t(bfm[ng], bb + (uint32_t)(k0 * (SV * 2) + (j0o + ng * 16) * 2) + offNT_SV);
                #pragma unroll
                for (int mt = 0; mt < 2; mt++)
                    #pragma unroll
                    for (int nt = 0; nt < 4; nt++)
                        mma16816(accO[mt][nt], af[mt], &bfm[nt >> 1][(nt & 1) * 2]);
            }
        }
    }

    // ---- epilogue ----
    float* Od = O + chbase + jh * 128;
    #pragma unroll
    for (int mt = 0; mt < 2; mt++)
        #pragma unroll
        for (int nt = 0; nt < 4; nt++) {
            int i = i0o + mt * 16 + g;
            int j = j0o + nt * 8 + 2 * q;
            float2 v0 = { accO[mt][nt][0], accO[mt][nt][1] };
            float2 v1 = { accO[mt][nt][2], accO[mt][nt][3] };
            *(float2*)(Od + (size_t)i * DD + j) = v0;
            *(float2*)(Od + (size_t)(i + 8) * DD + j) = v1;
        }
}

// ---------------------------------------------------------------------------
extern "C" void kernel_launch(void* const* d_in, const int* in_sizes, int n_in,
                              void* d_out, int out_size)
{
    const float* q    = (const float*)d_in[0];
    const float* k    = (const float*)d_in[1];
    const float* v    = (const float*)d_in[2];
    const float* beta = (const float*)d_in[3];
    float* out = (float*)d_out;
    (void)in_sizes; (void)n_in; (void)out_size;

    cudaFuncSetAttribute(dr_state, cudaFuncAttributeMaxDynamicSharedMemorySize, S_SMEM);
    cudaFuncSetAttribute(dr_out,   cudaFuncAttributeMaxDynamicSharedMemorySize, O_SMEM);

    dr_state<<<dim3(NBC, 4), 512, S_SMEM>>>(k, v, beta);
    dr_scan<<<dim3(64, BB), 256>>>();
    dr_out<<<dim3(NBC, 2), 512, O_SMEM>>>(q, k, v, out);
}

// round 6
// speedup vs baseline: 1.3274x; 1.3274x over previous
#include <cuda_runtime.h>
#include <cuda_bf16.h>
#include <cstdint>
#include <cstddef>

#define BB 8
#define SS 4096
#define DD 256
#define CC 64
#define NCHUNK 64
#define NBC (BB * NCHUNK)   // 512

// Scratch: S^T per chunk [bc][j][i]; scan converts in place to H^T (state
// entering chunk). 134 MB fp32.
__device__ float g_S[(size_t)NBC * DD * DD];
__device__ float g_Lg[NBC * CC];
__device__ float g_Gamma[NBC];

// ---------------------------------------------------------------------------
// Helpers
// ---------------------------------------------------------------------------
__device__ __forceinline__ uint32_t smem_u32(const void* p) {
    uint32_t a;
    asm("{ .reg .u64 t; cvta.to.shared.u64 t, %1; cvt.u32.u64 %0, t; }"
        : "=r"(a) : "l"(p));
    return a;
}

__device__ __forceinline__ float to_tf32(float f) {
    uint32_t r;
    asm("cvt.rna.tf32.f32 %0, %1;" : "=r"(r) : "f"(f));
    return __uint_as_float(r);
}

__device__ __forceinline__ void mma_tf32(float c[4], const uint32_t a[4],
                                         const uint32_t b[2]) {
    asm volatile(
        "mma.sync.aligned.m16n8k8.row.col.f32.tf32.tf32.f32 "
        "{%0,%1,%2,%3}, {%4,%5,%6,%7}, {%8,%9}, {%0,%1,%2,%3};"
        : "+f"(c[0]), "+f"(c[1]), "+f"(c[2]), "+f"(c[3])
        : "r"(a[0]), "r"(a[1]), "r"(a[2]), "r"(a[3]), "r"(b[0]), "r"(b[1]));
}

// fp32 "ldmatrix trick": one b16 8x8 ldmatrix = one 8x4-fp32 tile whose
// thread->element map equals the tf32 fragment layout.
__device__ __forceinline__ void ldmx4(uint32_t r[4], uint32_t a) {
    asm volatile("ldmatrix.sync.aligned.m8n8.x4.shared.b16 {%0,%1,%2,%3}, [%4];"
                 : "=r"(r[0]), "=r"(r[1]), "=r"(r[2]), "=r"(r[3]) : "r"(a));
}
__device__ __forceinline__ void ldmx2(uint32_t r[2], uint32_t a) {
    asm volatile("ldmatrix.sync.aligned.m8n8.x2.shared.b16 {%0,%1}, [%2];"
                 : "=r"(r[0]), "=r"(r[1]) : "r"(a));
}

// padded fp32 strides, all ≡ 4 (mod 32) words -> conflict-free ldmatrix rows
#define SQO 260   // 256-wide
#define SVO 132   // 128-wide
#define SAS 68    // 64-wide

// ---------------------------------------------------------------------------
// Kernel A: S^T quadrant [j 128][i 128] per CTA; grid (NBC, 4), 256 thr.
//   ST[j][i] = sum_tau V[tau][j] * (w_tau K[tau][i])
// A-frags from V [k][m] (transposed -> per-thread LDS), B from wK [k][n].
// ---------------------------------------------------------------------------
#define S_WV   0
#define S_LG   256
#define S_V    512
#define S_K    (S_V + 64 * SVO * 4)     // +33792
#define S_SMEM (S_K + 64 * SVO * 4)     // 68096

__global__ __launch_bounds__(256, 2) void dr_state(
    const float* __restrict__ K, const float* __restrict__ V,
    const float* __restrict__ beta)
{
    extern __shared__ char sm[];
    float* wv  = (float*)(sm + S_WV);
    float* sLg = (float*)(sm + S_LG);
    float* Vs  = (float*)(sm + S_V);
    float* Ks  = (float*)(sm + S_K);
    const int bc = blockIdx.x;
    const int qj = blockIdx.y >> 1, qi = blockIdx.y & 1;
    const int b = bc >> 6, c = bc & 63;
    const int tid = threadIdx.x, wid = tid >> 5, lane = tid & 31;
    const int q = lane & 3, g = lane >> 2;

    if (tid < CC) sLg[tid] = __logf(fmaxf(beta[b * SS + c * CC + tid], 1e-30f));
    __syncthreads();
    if (tid == 0) {
        float s = 0.f;
        #pragma unroll
        for (int u = 0; u < CC; u++) { s += sLg[u]; sLg[u] = s; }
    }
    __syncthreads();
    const float LgEnd = sLg[CC - 1];
    if (tid < CC) {
        wv[tid] = __expf(LgEnd - sLg[tid]);
        if (blockIdx.y == 0) g_Lg[bc * CC + tid] = sLg[tid];
    }
    if (blockIdx.y == 0 && tid == 0) g_Gamma[bc] = __expf(LgEnd);
    __syncthreads();

    const float* Kg = K + ((size_t)b * SS + (size_t)c * CC) * DD + qi * 128;
    const float* Vg = V + ((size_t)b * SS + (size_t)c * CC) * DD + qj * 128;

    #pragma unroll
    for (int it = 0; it < 8; it++) {
        int idx = it * 256 + tid;                  // 0..2047
        int tau = idx >> 5, c4 = (idx & 31) << 2;
        float wt = wv[tau];
        float4 kq = *(const float4*)(Kg + (size_t)tau * DD + c4);
        Ks[tau * SVO + c4 + 0] = to_tf32(kq.x * wt);
        Ks[tau * SVO + c4 + 1] = to_tf32(kq.y * wt);
        Ks[tau * SVO + c4 + 2] = to_tf32(kq.z * wt);
        Ks[tau * SVO + c4 + 3] = to_tf32(kq.w * wt);
        float4 vq = *(const float4*)(Vg + (size_t)tau * DD + c4);
        Vs[tau * SVO + c4 + 0] = to_tf32(vq.x);
        Vs[tau * SVO + c4 + 1] = to_tf32(vq.y);
        Vs[tau * SVO + c4 + 2] = to_tf32(vq.z);
        Vs[tau * SVO + c4 + 3] = to_tf32(vq.w);
    }
    __syncthreads();

    const int j0w = (wid >> 1) * 32;   // 4 j-tiles of 32
    const int i0w = (wid & 1) * 64;    // 2 i-tiles of 64

    float acc[2][8][4];
    #pragma unroll
    for (int mt = 0; mt < 2; mt++)
        #pragma unroll
        for (int nt = 0; nt < 8; nt++)
            #pragma unroll
            for (int u = 0; u < 4; u++) acc[mt][nt][u] = 0.f;

    #pragma unroll
    for (int k0 = 0; k0 < 64; k0 += 8) {
        uint32_t af[2][4], bf[8][2];
        const int r0 = (k0 + q) * SVO, r4 = (k0 + 4 + q) * SVO;
        #pragma unroll
        for (int mt = 0; mt < 2; mt++) {
            int jb = j0w + mt * 16 + g;
            af[mt][0] = __float_as_uint(Vs[r0 + jb]);
            af[mt][1] = __float_as_uint(Vs[r0 + jb + 8]);
            af[mt][2] = __float_as_uint(Vs[r4 + jb]);
            af[mt][3] = __float_as_uint(Vs[r4 + jb + 8]);
        }
        #pragma unroll
        for (int nt = 0; nt < 8; nt++) {
            int ib = i0w + nt * 8 + g;
            bf[nt][0] = __float_as_uint(Ks[r0 + ib]);
            bf[nt][1] = __float_as_uint(Ks[r4 + ib]);
        }
        #pragma unroll
        for (int mt = 0; mt < 2; mt++)
            #pragma unroll
            for (int nt = 0; nt < 8; nt++)
                mma_tf32(acc[mt][nt], af[mt], bf[nt]);
    }

    float* Sdst = g_S + (size_t)bc * 65536 + (size_t)(qj * 128) * 256 + qi * 128;
    #pragma unroll
    for (int mt = 0; mt < 2; mt++)
        #pragma unroll
        for (int nt = 0; nt < 8; nt++) {
            int j = j0w + mt * 16 + g;
            int i = i0w + nt * 8 + 2 * q;
            float2 v0 = { acc[mt][nt][0], acc[mt][nt][1] };
            float2 v1 = { acc[mt][nt][2], acc[mt][nt][3] };
            *(float2*)(Sdst + (size_t)j * 256 + i) = v0;
            *(float2*)(Sdst + (size_t)(j + 8) * 256 + i) = v1;
        }
}

// ---------------------------------------------------------------------------
// Kernel B: cross-chunk scan, in place (g_S becomes H^T entering each chunk).
// ---------------------------------------------------------------------------
__global__ __launch_bounds__(256) void dr_scan()
{
    const int b = blockIdx.y;
    const int tid = threadIdx.x;
    const size_t e4 = ((size_t)blockIdx.x * 256 + tid) * 4;
    __shared__ float gam[NCHUNK];
    if (tid < NCHUNK) gam[tid] = g_Gamma[b * NCHUNK + tid];
    __syncthreads();

    float4 h = { 0.f, 0.f, 0.f, 0.f };
    const size_t base = (size_t)b * NCHUNK * 65536 + e4;
    for (int c = 0; c < NCHUNK; c++) {
        const size_t off = base + (size_t)c * 65536;
        float4 s = *(const float4*)(g_S + off);
        *(float4*)(g_S + off) = h;
        float gc = gam[c];
        h.x = gc * h.x + s.x; h.y = gc * h.y + s.y;
        h.z = gc * h.z + s.z; h.w = gc * h.w + s.w;
    }
}

// ---------------------------------------------------------------------------
// Kernel C: fused output per bc (512 threads):
//   A_att = mask(QK^T) (once); then per j-half:
//   O[:, jh] = g_i * (Q @ H^T[jh rows]) + A_att @ V[:, jh]
// ---------------------------------------------------------------------------
#define O_LG   0
#define O_SG   256
#define O_Q    1024
#define O_KH   (O_Q + 64 * SQO * 4)     // +66560 -> 67584 (K, then H panels 128*SVO*4=67584)
#define O_V    (O_KH + 128 * SVO * 4)   // 135168
#define O_AS   (O_V + 64 * SVO * 4)     // 168960
#define O_SMEM (O_AS + 64 * SAS * 4)    // 186368

__global__ __launch_bounds__(512) void dr_out(
    const float* __restrict__ Q, const float* __restrict__ K,
    const float* __restrict__ V, float* __restrict__ O)
{
    extern __shared__ char sm[];
    float* sLg = (float*)(sm + O_LG);
    float* sg  = (float*)(sm + O_SG);
    float* Qs  = (float*)(sm + O_Q);
    float* KHs = (float*)(sm + O_KH);
    float* Vs  = (float*)(sm + O_V);
    float* As  = (float*)(sm + O_AS);
    const int bc = blockIdx.x;
    const int b = bc >> 6, c = bc & 63;
    const int tid = threadIdx.x, wid = tid >> 5, lane = tid & 31;
    const int q = lane & 3, g = lane >> 2;
    const int rA = lane & 15, cA = (lane >> 4) * 4;       // A-frag ldmatrix map
    const int rB = lane & 7,  cB = ((lane >> 3) & 1) * 4; // B-frag ldmatrix map

    if (tid < CC) {
        float lg = g_Lg[bc * CC + tid];
        sLg[tid] = lg;
        sg[tid]  = __expf(lg);
    }

    const size_t chbase = ((size_t)b * SS + (size_t)c * CC) * DD;
    #pragma unroll
    for (int it = 0; it < 8; it++) {
        int idx = it * 512 + tid;                  // 0..4095
        int row = idx >> 6, c4 = (idx & 63) << 2;
        float4 qv = *(const float4*)(Q + chbase + (size_t)row * DD + c4);
        Qs[row * SQO + c4 + 0] = to_tf32(qv.x);
        Qs[row * SQO + c4 + 1] = to_tf32(qv.y);
        Qs[row * SQO + c4 + 2] = to_tf32(qv.z);
        Qs[row * SQO + c4 + 3] = to_tf32(qv.w);
        float4 kv = *(const float4*)(K + chbase + (size_t)row * DD + c4);
        KHs[row * SQO + c4 + 0] = to_tf32(kv.x);
        KHs[row * SQO + c4 + 1] = to_tf32(kv.y);
        KHs[row * SQO + c4 + 2] = to_tf32(kv.z);
        KHs[row * SQO + c4 + 3] = to_tf32(kv.w);
    }
    __syncthreads();

    const uint32_t qb = smem_u32(Qs), kb = smem_u32(KHs);
    const uint32_t vb = smem_u32(Vs), ab = smem_u32(As);

    // ---- Phase 1: QK^T -> A_att (16 warps, 16x16 tiles) ----
    const int i0 = (wid >> 2) * 16, t0 = (wid & 3) * 16;
    {
        float acc1[2][4];
        #pragma unroll
        for (int nt = 0; nt < 2; nt++)
            #pragma unroll
            for (int u = 0; u < 4; u++) acc1[nt][u] = 0.f;

        #pragma unroll
        for (int k0 = 0; k0 < 256; k0 += 8) {
            uint32_t af[4], bf[2][2];
            ldmx4(af, qb + (uint32_t)(((i0 + rA) * SQO + k0 + cA) * 4));
            #pragma unroll
            for (int nt = 0; nt < 2; nt++)
                ldmx2(bf[nt], kb + (uint32_t)(((t0 + nt * 8 + rB) * SQO + k0 + cB) * 4));
            #pragma unroll
            for (int nt = 0; nt < 2; nt++)
                mma_tf32(acc1[nt], af, bf[nt]);
        }

        #pragma unroll
        for (int nt = 0; nt < 2; nt++) {
            int ia = i0 + g, ib2 = ia + 8;
            int t = t0 + nt * 8 + 2 * q;
            float la = sLg[ia], lb = sLg[ib2], l0 = sLg[t], l1 = sLg[t + 1];
            float f00 = (t     <= ia)  ? __expf(la - l0) : 0.f;
            float f01 = (t + 1 <= ia)  ? __expf(la - l1) : 0.f;
            float f10 = (t     <= ib2) ? __expf(lb - l0) : 0.f;
            float f11 = (t + 1 <= ib2) ? __expf(lb - l1) : 0.f;
            float2 v0 = { to_tf32(acc1[nt][0] * f00), to_tf32(acc1[nt][1] * f01) };
            float2 v1 = { to_tf32(acc1[nt][2] * f10), to_tf32(acc1[nt][3] * f11) };
            *(float2*)(As + ia * SAS + t)  = v0;
            *(float2*)(As + ib2 * SAS + t) = v1;
        }
    }
    __syncthreads();   // As published; K region free

    const int j0 = (wid & 3) * 32;   // output warp tile: 16 i x 32 j

    for (int jh = 0; jh < 2; jh++) {
        // V half -> smem (tf32)
        #pragma unroll
        for (int it = 0; it < 4; it++) {
            int idx = it * 512 + tid;              // 0..2047
            int row = idx >> 5, c4 = (idx & 31) << 2;
            float4 vv = *(const float4*)(V + chbase + (size_t)row * DD + jh * 128 + c4);
            Vs[row * SVO + c4 + 0] = to_tf32(vv.x);
            Vs[row * SVO + c4 + 1] = to_tf32(vv.y);
            Vs[row * SVO + c4 + 2] = to_tf32(vv.z);
            Vs[row * SVO + c4 + 3] = to_tf32(vv.w);
        }
        __syncthreads();

        float accAV[4][4], accQH[4][4];
        #pragma unroll
        for (int nt = 0; nt < 4; nt++)
            #pragma unroll
            for (int u = 0; u < 4; u++) { accAV[nt][u] = 0.f; accQH[nt][u] = 0.f; }

        // ---- A_att @ V (K-dim 64; B via per-thread LDS from V[k][n]) ----
        #pragma unroll
        for (int k0 = 0; k0 < 64; k0 += 8) {
            uint32_t af[4], bf[4][2];
            ldmx4(af, ab + (uint32_t)(((i0 + rA) * SAS + k0 + cA) * 4));
            const int r0 = (k0 + q) * SVO, r4 = (k0 + 4 + q) * SVO;
            #pragma unroll
            for (int nt = 0; nt < 4; nt++) {
                int jb = j0 + nt * 8 + g;
                bf[nt][0] = __float_as_uint(Vs[r0 + jb]);
                bf[nt][1] = __float_as_uint(Vs[r4 + jb]);
            }
            #pragma unroll
            for (int nt = 0; nt < 4; nt++)
                mma_tf32(accAV[nt], af, bf[nt]);
        }

        // ---- Q @ H^T (K-dim 256, two 128-col panels staged in KH region) ----
        for (int p = 0; p < 2; p++) {
            __syncthreads();   // prior users of KH region done
            #pragma unroll
            for (int it = 0; it < 8; it++) {
                int idx = it * 512 + tid;          // 0..4095
                int row = idx >> 5, c4 = (idx & 31) << 2;
                float4 hv = *(const float4*)(g_S + (size_t)bc * 65536 +
                                             (size_t)(jh * 128 + row) * 256 + p * 128 + c4);
                KHs[row * SVO + c4 + 0] = to_tf32(hv.x);
                KHs[row * SVO + c4 + 1] = to_tf32(hv.y);
                KHs[row * SVO + c4 + 2] = to_tf32(hv.z);
                KHs[row * SVO + c4 + 3] = to_tf32(hv.w);
            }
            __syncthreads();
            #pragma unroll
            for (int k0 = 0; k0 < 128; k0 += 8) {
                uint32_t af[4], bf[4][2];
                ldmx4(af, qb + (uint32_t)(((i0 + rA) * SQO + p * 128 + k0 + cA) * 4));
                #pragma unroll
                for (int nt = 0; nt < 4; nt++)
                    ldmx2(bf[nt], kb + (uint32_t)(((j0 + nt * 8 + rB) * SVO + k0 + cB) * 4));
                #pragma unroll
                for (int nt = 0; nt < 4; nt++)
                    mma_tf32(accQH[nt], af, bf[nt]);
            }
        }

        // ---- epilogue ----
        float* Od = O + chbase + jh * 128;
        #pragma unroll
        for (int nt = 0; nt < 4; nt++) {
            int ia = i0 + g, ib2 = ia + 8;
            int j = j0 + nt * 8 + 2 * q;
            float sa = sg[ia], sb2 = sg[ib2];
            float2 v0 = { sa * accQH[nt][0] + accAV[nt][0],
                          sa * accQH[nt][1] + accAV[nt][1] };
            float2 v1 = { sb2 * accQH[nt][2] + accAV[nt][2],
                          sb2 * accQH[nt][3] + accAV[nt][3] };
            *(float2*)(Od + (size_t)ia * DD + j)  = v0;
            *(float2*)(Od + (size_t)ib2 * DD + j) = v1;
        }
        __syncthreads();   // V region safe to reload next jh
    }
}

// ---------------------------------------------------------------------------
extern "C" void kernel_launch(void* const* d_in, const int* in_sizes, int n_in,
                              void* d_out, int out_size)
{
    const float* q    = (const float*)d_in[0];
    const float* k    = (const float*)d_in[1];
    const float* v    = (const float*)d_in[2];
    const float* beta = (const float*)d_in[3];
    float* out = (float*)d_out;
    (void)in_sizes; (void)n_in; (void)out_size;

    cudaFuncSetAttribute(dr_state, cudaFuncAttributeMaxDynamicSharedMemorySize, S_SMEM);
    cudaFuncSetAttribute(dr_out,   cudaFuncAttributeMaxDynamicSharedMemorySize, O_SMEM);

    dr_state<<<dim3(NBC, 4), 256, S_SMEM>>>(k, v, beta);
    dr_scan<<<dim3(64, BB), 256>>>();
    dr_out<<<NBC, 512, O_SMEM>>>(q, k, v, out);
}

// round 8
// speedup vs baseline: 1.6634x; 1.2532x over previous
#include <cuda_runtime.h>
#include <cstdint>
#include <cstddef>

#define BB 8
#define SS 4096
#define DD 256
#define GG 512      // big chunk
#define NG 8        // big chunks per batch
#define NBG 64      // total big chunks
#define CI 32       // inner chunk
#define NIC 16      // inner chunks per big chunk

// Scratch: per-big-chunk state^T [bg][j][d]; LB converts in place to the
// state ENTERING each big chunk. Only 16.8 MB.
__device__ float g_S[(size_t)NBG * DD * DD];
__device__ float g_Lg[NBG * GG];
__device__ float g_Gamma[NBG];

// ---------------------------------------------------------------------------
// Helpers (base-ISA tf32 path, proven in R6)
// ---------------------------------------------------------------------------
__device__ __forceinline__ uint32_t smem_u32(const void* p) {
    uint32_t a;
    asm("{ .reg .u64 t; cvta.to.shared.u64 t, %1; cvt.u32.u64 %0, t; }"
        : "=r"(a) : "l"(p));
    return a;
}

__device__ __forceinline__ float to_tf32(float f) {
    uint32_t r;
    asm("cvt.rna.tf32.f32 %0, %1;" : "=r"(r) : "f"(f));
    return __uint_as_float(r);
}

__device__ __forceinline__ void mma_tf32(float c[4], const uint32_t a[4],
                                         const uint32_t b[2]) {
    asm volatile(
        "mma.sync.aligned.m16n8k8.row.col.f32.tf32.tf32.f32 "
        "{%0,%1,%2,%3}, {%4,%5,%6,%7}, {%8,%9}, {%0,%1,%2,%3};"
        : "+f"(c[0]), "+f"(c[1]), "+f"(c[2]), "+f"(c[3])
        : "r"(a[0]), "r"(a[1]), "r"(a[2]), "r"(a[3]), "r"(b[0]), "r"(b[1]));
}

__device__ __forceinline__ void ldmx4(uint32_t r[4], uint32_t a) {
    asm volatile("ldmatrix.sync.aligned.m8n8.x4.shared.b16 {%0,%1,%2,%3}, [%4];"
                 : "=r"(r[0]), "=r"(r[1]), "=r"(r[2]), "=r"(r[3]) : "r"(a));
}
__device__ __forceinline__ void ldmx2(uint32_t r[2], uint32_t a) {
    asm volatile("ldmatrix.sync.aligned.m8n8.x2.shared.b16 {%0,%1}, [%2];"
                 : "=r"(r[0]), "=r"(r[1]) : "r"(a));
}

// fp32 smem strides (words), ≡ 4 (mod 32): conflict-free b16-trick ldmatrix
#define SD4 260   // 256-wide rows
#define SV4 132   // 128-wide rows
#define SA4 36    // 32-wide rows

// ---------------------------------------------------------------------------
// LA: big-chunk state contribution T^T[j][d] per (bg, j-half). 512 threads.
//   T[j][d] = sum_{tau<512} V[tau][j] * (w_tau K[tau][d]),  w = exp(LgEnd-Lg)
// ---------------------------------------------------------------------------
#define A_LGG 0
#define A_WV  2048
#define A_V   4096
#define A_K   (A_V + 64 * SV4 * 4)     // 4096 + 33792 = 37888
#define A_SMEM (A_K + 64 * SD4 * 4)    // 37888 + 66560 = 104448

__global__ __launch_bounds__(512, 1) void dr_state(
    const float* __restrict__ K, const float* __restrict__ V,
    const float* __restrict__ beta)
{
    extern __shared__ char sm[];
    float* Lgg = (float*)(sm + A_LGG);
    float* wv  = (float*)(sm + A_WV);
    float* Vs  = (float*)(sm + A_V);
    float* Ks  = (float*)(sm + A_K);
    const int bg = blockIdx.x, qj = blockIdx.y;
    const int b = bg >> 3, g2 = bg & 7;
    const int tid = threadIdx.x, wid = tid >> 5, lane = tid & 31;
    const int q = lane & 3, g = lane >> 2;

    const size_t tok0 = (size_t)b * SS + (size_t)g2 * GG;

    // cumulative log(beta) over the big chunk
    if (tid < GG) Lgg[tid] = __logf(fmaxf(beta[tok0 + tid], 1e-30f));
    __syncthreads();
    if (wid == 0) {
        int b0 = lane * 16;
        float s = 0.f;
        #pragma unroll
        for (int u = 0; u < 16; u++) { s += Lgg[b0 + u]; Lgg[b0 + u] = s; }
        float t = s;
        #pragma unroll
        for (int d = 1; d < 32; d <<= 1) {
            float o = __shfl_up_sync(0xFFFFFFFFu, t, d);
            if (lane >= d) t += o;
        }
        float excl = t - s;
        #pragma unroll
        for (int u = 0; u < 16; u++) Lgg[b0 + u] += excl;
    }
    __syncthreads();
    const float lend = Lgg[GG - 1];
    if (tid < GG) {
        wv[tid] = __expf(lend - Lgg[tid]);
        if (qj == 0) g_Lg[bg * GG + tid] = Lgg[tid];
    }
    if (qj == 0 && tid == 0) g_Gamma[bg] = __expf(lend);

    const float* Kg = K + tok0 * DD;
    const float* Vg = V + tok0 * DD + qj * 128;

    const int jm0 = (wid >> 2) * 32;   // 4 j-tiles of 32
    const int i0w = (wid & 3) * 64;    // 4 d-tiles of 64

    float acc[2][8][4];
    #pragma unroll
    for (int mt = 0; mt < 2; mt++)
        #pragma unroll
        for (int nt = 0; nt < 8; nt++)
            #pragma unroll
            for (int u = 0; u < 4; u++) acc[mt][nt][u] = 0.f;

    for (int p = 0; p < 8; p++) {
        __syncthreads();
        // K panel (64 x 256) scaled by w
        #pragma unroll
        for (int it = 0; it < 8; it++) {
            int idx = it * 512 + tid;              // 0..4095
            int tau = idx >> 6, c4 = (idx & 63) << 2;
            int tg = p * 64 + tau;
            float wt = wv[tg];
            float4 kq = *(const float4*)(Kg + (size_t)tg * DD + c4);
            Ks[tau * SD4 + c4 + 0] = to_tf32(kq.x * wt);
            Ks[tau * SD4 + c4 + 1] = to_tf32(kq.y * wt);
            Ks[tau * SD4 + c4 + 2] = to_tf32(kq.z * wt);
            Ks[tau * SD4 + c4 + 3] = to_tf32(kq.w * wt);
        }
        // V panel half (64 x 128)
        #pragma unroll
        for (int it = 0; it < 4; it++) {
            int idx = it * 512 + tid;              // 0..2047
            int tau = idx >> 5, c4 = (idx & 31) << 2;
            int tg = p * 64 + tau;
            float4 vq = *(const float4*)(Vg + (size_t)tg * DD + c4);
            Vs[tau * SV4 + c4 + 0] = to_tf32(vq.x);
            Vs[tau * SV4 + c4 + 1] = to_tf32(vq.y);
            Vs[tau * SV4 + c4 + 2] = to_tf32(vq.z);
            Vs[tau * SV4 + c4 + 3] = to_tf32(vq.w);
        }
        __syncthreads();

        #pragma unroll
        for (int k0 = 0; k0 < 64; k0 += 8) {
            const int r0 = (k0 + q) * SV4, r4 = (k0 + 4 + q) * SV4;
            const int s0 = (k0 + q) * SD4, s4 = (k0 + 4 + q) * SD4;
            uint32_t af[2][4], bf[8][2];
            #pragma unroll
            for (int mt = 0; mt < 2; mt++) {
                int jb = jm0 + mt * 16 + g;
                af[mt][0] = __float_as_uint(Vs[r0 + jb]);
                af[mt][1] = __float_as_uint(Vs[r0 + jb + 8]);
                af[mt][2] = __float_as_uint(Vs[r4 + jb]);
                af[mt][3] = __float_as_uint(Vs[r4 + jb + 8]);
            }
            #pragma unroll
            for (int nt = 0; nt < 8; nt++) {
                int db = i0w + nt * 8 + g;
                bf[nt][0] = __float_as_uint(Ks[s0 + db]);
                bf[nt][1] = __float_as_uint(Ks[s4 + db]);
            }
            #pragma unroll
            for (int mt = 0; mt < 2; mt++)
                #pragma unroll
                for (int nt = 0; nt < 8; nt++)
                    mma_tf32(acc[mt][nt], af[mt], bf[nt]);
        }
    }

    float* Sdst = g_S + (size_t)bg * 65536 + (size_t)(qj * 128) * 256;
    #pragma unroll
    for (int mt = 0; mt < 2; mt++)
        #pragma unroll
        for (int nt = 0; nt < 8; nt++) {
            int j = jm0 + mt * 16 + g;
            int d = i0w + nt * 8 + 2 * q;
            float2 v0 = { acc[mt][nt][0], acc[mt][nt][1] };
            float2 v1 = { acc[mt][nt][2], acc[mt][nt][3] };
            *(float2*)(Sdst + (size_t)j * 256 + d) = v0;
            *(float2*)(Sdst + (size_t)(j + 8) * 256 + d) = v1;
        }
}

// ---------------------------------------------------------------------------
// LB: 8-step scan over big-chunk states (in place -> state entering bg).
// ---------------------------------------------------------------------------
__global__ __launch_bounds__(256) void dr_scan()
{
    const int b = blockIdx.y;
    const size_t e4 = ((size_t)blockIdx.x * 256 + threadIdx.x) * 4;
    float4 h = { 0.f, 0.f, 0.f, 0.f };
    #pragma unroll
    for (int g2 = 0; g2 < NG; g2++) {
        const int bg = b * NG + g2;
        const size_t off = (size_t)bg * 65536 + e4;
        const float gc = g_Gamma[bg];
        float4 s = *(const float4*)(g_S + off);
        *(float4*)(g_S + off) = h;
        h.x = gc * h.x + s.x; h.y = gc * h.y + s.y;
        h.z = gc * h.z + s.z; h.w = gc * h.w + s.w;
    }
}

// ---------------------------------------------------------------------------
// LC: fused per-(bg, j-half) kernel. State H^T[j 128][d 256] carried in
// registers (fp32, 64/thread as update-MMA accumulators) + tf32 smem shadow.
// Walks 16 inner chunks of 32 tokens: O = g*(Q@H) + mask(QK^T)@V, then
// H <- gamma*H + (wV)^T K accumulated straight into the state registers.
// ---------------------------------------------------------------------------
#define O_LGG 0                         // 2048
#define O_WV  2048                      // 128
#define O_SG  2176                      // 128
#define O_H   2560                      // 128*260*4 = 133120 -> 135680
#define O_Q   135680                    // 32*260*4  = 33280  -> 168960
#define O_K   168960                    //                     -> 202240
#define O_V   202240                    // 32*132*4  = 16896  -> 219136
#define O_A   219136                    // 32*36*4   = 4608   -> 223744
#define O_SMEM 223744

__global__ __launch_bounds__(512, 1) void dr_out(
    const float* __restrict__ Q, const float* __restrict__ K,
    const float* __restrict__ V, float* __restrict__ O)
{
    extern __shared__ char sm[];
    float* Lgg = (float*)(sm + O_LGG);
    float* wv  = (float*)(sm + O_WV);
    float* sg  = (float*)(sm + O_SG);
    float* Hs  = (float*)(sm + O_H);
    float* Qs  = (float*)(sm + O_Q);
    float* Ks  = (float*)(sm + O_K);
    float* Vs  = (float*)(sm + O_V);
    float* As  = (float*)(sm + O_A);

    const int bg = blockIdx.x, jh = blockIdx.y;
    const int b = bg >> 3, g2 = bg & 7;
    const int tid = threadIdx.x, wid = tid >> 5, lane = tid & 31;
    const int q = lane & 3, g = lane >> 2;
    const int rA = lane & 15, cA = (lane >> 4) * 4;
    const int rB = lane & 7,  cB = ((lane >> 3) & 1) * 4;

    Lgg[tid] = g_Lg[bg * GG + tid];

    const size_t tok0 = (size_t)b * SS + (size_t)g2 * GG;

    // H_in -> Hs (tf32 shadow), coalesced
    #pragma unroll
    for (int it = 0; it < 16; it++) {
        int idx = it * 512 + tid;                  // 0..8191
        int row = idx >> 6, c4 = (idx & 63) << 2;
        float4 hv = *(const float4*)(g_S + (size_t)bg * 65536 +
                                     (size_t)(jh * 128 + row) * 256 + c4);
        Hs[row * SD4 + c4 + 0] = to_tf32(hv.x);
        Hs[row * SD4 + c4 + 1] = to_tf32(hv.y);
        Hs[row * SD4 + c4 + 2] = to_tf32(hv.z);
        Hs[row * SD4 + c4 + 3] = to_tf32(hv.w);
    }
    __syncthreads();

    // state registers: warp update-tile [j 16][d 128]
    const int jm0 = (wid >> 1) * 16;
    const int nb0 = (wid & 1) * 128;
    float st[16][4];
    #pragma unroll
    for (int nt = 0; nt < 16; nt++) {
        int d0 = nb0 + nt * 8 + 2 * q;
        st[nt][0] = Hs[(jm0 + g) * SD4 + d0];
        st[nt][1] = Hs[(jm0 + g) * SD4 + d0 + 1];
        st[nt][2] = Hs[(jm0 + 8 + g) * SD4 + d0];
        st[nt][3] = Hs[(jm0 + 8 + g) * SD4 + d0 + 1];
    }

    const uint32_t qb = smem_u32(Qs), kb = smem_u32(Ks);
    const uint32_t hb = smem_u32(Hs), ab = smem_u32(As);
    const int i0q = (wid >> 2) * 16, t0q = (wid & 3) * 8;   // QK tiling (wid<8)
    const int i0m = (wid >> 3) * 16, j0 = (wid & 7) * 16;   // O tiling

    for (int ic = 0; ic < NIC; ic++) {
        const int icb = ic * CI;
        __syncthreads();                                    // S0
        const float baseL = ic ? Lgg[icb - 1] : 0.f;
        const float lendI = Lgg[icb + CI - 1];
        if (tid < CI) {
            float lt = Lgg[icb + tid];
            wv[tid] = __expf(lendI - lt);
            sg[tid] = __expf(lt - baseL);
        }
        #pragma unroll
        for (int it = 0; it < 4; it++) {
            int idx = it * 512 + tid;                       // 0..2047
            int row = idx >> 6, c4 = (idx & 63) << 2;
            float4 qv = *(const float4*)(Q + (tok0 + icb + row) * DD + c4);
            Qs[row * SD4 + c4 + 0] = to_tf32(qv.x);
            Qs[row * SD4 + c4 + 1] = to_tf32(qv.y);
            Qs[row * SD4 + c4 + 2] = to_tf32(qv.z);
            Qs[row * SD4 + c4 + 3] = to_tf32(qv.w);
            float4 kv = *(const float4*)(K + (tok0 + icb + row) * DD + c4);
            Ks[row * SD4 + c4 + 0] = to_tf32(kv.x);
            Ks[row * SD4 + c4 + 1] = to_tf32(kv.y);
            Ks[row * SD4 + c4 + 2] = to_tf32(kv.z);
            Ks[row * SD4 + c4 + 3] = to_tf32(kv.w);
        }
        #pragma unroll
        for (int it = 0; it < 2; it++) {
            int idx = it * 512 + tid;                       // 0..1023
            int row = idx >> 5, c4 = (idx & 31) << 2;
            float4 vv = *(const float4*)(V + (tok0 + icb + row) * DD + jh * 128 + c4);
            Vs[row * SV4 + c4 + 0] = to_tf32(vv.x);
            Vs[row * SV4 + c4 + 1] = to_tf32(vv.y);
            Vs[row * SV4 + c4 + 2] = to_tf32(vv.z);
            Vs[row * SV4 + c4 + 3] = to_tf32(vv.w);
        }
        __syncthreads();                                    // S1

        // ---- QK^T (warps 0..7, m16n8 tiles over [32 x 32]) ----
        if (wid < 8) {
            float a1[4] = { 0.f, 0.f, 0.f, 0.f };
            #pragma unroll
            for (int k0 = 0; k0 < 256; k0 += 8) {
                uint32_t af[4], bf[2];
                ldmx4(af, qb + (uint32_t)(((i0q + rA) * SD4 + k0 + cA) * 4));
                ldmx2(bf, kb + (uint32_t)(((t0q + rB) * SD4 + k0 + cB) * 4));
                mma_tf32(a1, af, bf);
            }
            int ia = i0q + g, ib2 = ia + 8, t = t0q + 2 * q;
            float lia = Lgg[icb + ia], lib = Lgg[icb + ib2];
            float lt0 = Lgg[icb + t], lt1 = Lgg[icb + t + 1];
            float f00 = (t     <= ia)  ? __expf(lia - lt0) : 0.f;
            float f01 = (t + 1 <= ia)  ? __expf(lia - lt1) : 0.f;
            float f10 = (t     <= ib2) ? __expf(lib - lt0) : 0.f;
            float f11 = (t + 1 <= ib2) ? __expf(lib - lt1) : 0.f;
            float2 w0 = { to_tf32(a1[0] * f00), to_tf32(a1[1] * f01) };
            float2 w1 = { to_tf32(a1[2] * f10), to_tf32(a1[3] * f11) };
            *(float2*)(As + ia * SA4 + t)  = w0;
            *(float2*)(As + ib2 * SA4 + t) = w1;
        }
        __syncthreads();                                    // S2

        // ---- O tile [32 i][128 j]: Q@H, scale by g, then +A@V ----
        float acc[2][4];
        #pragma unroll
        for (int nt = 0; nt < 2; nt++)
            #pragma unroll
            for (int u = 0; u < 4; u++) acc[nt][u] = 0.f;

        #pragma unroll
        for (int k0 = 0; k0 < 256; k0 += 8) {
            uint32_t af[4], bf[2][2];
            ldmx4(af, qb + (uint32_t)(((i0m + rA) * SD4 + k0 + cA) * 4));
            #pragma unroll
            for (int nt = 0; nt < 2; nt++)
                ldmx2(bf[nt], hb + (uint32_t)(((j0 + nt * 8 + rB) * SD4 + k0 + cB) * 4));
            #pragma unroll
            for (int nt = 0; nt < 2; nt++)
                mma_tf32(acc[nt], af, bf[nt]);
        }
        {
            float sa = sg[i0m + g], sb2 = sg[i0m + 8 + g];
            #pragma unroll
            for (int nt = 0; nt < 2; nt++) {
                acc[nt][0] *= sa;  acc[nt][1] *= sa;
                acc[nt][2] *= sb2; acc[nt][3] *= sb2;
            }
        }
        #pragma unroll
        for (int k0 = 0; k0 < CI; k0 += 8) {
            uint32_t af[4];
            ldmx4(af, ab + (uint32_t)(((i0m + rA) * SA4 + k0 + cA) * 4));
            #pragma unroll
            for (int nt = 0; nt < 2; nt++) {
                int jc = j0 + nt * 8 + g;
                uint32_t bf[2] = {
                    __float_as_uint(Vs[(k0 + q) * SV4 + jc]),
                    __float_as_uint(Vs[(k0 + 4 + q) * SV4 + jc]) };
                mma_tf32(acc[nt], af, bf);
            }
        }
        {
            size_t r0 = (tok0 + icb + i0m + g) * DD + jh * 128;
            size_t r1 = (tok0 + icb + i0m + 8 + g) * DD + jh * 128;
            #pragma unroll
            for (int nt = 0; nt < 2; nt++) {
                int j = j0 + nt * 8 + 2 * q;
                float2 v0 = { acc[nt][0], acc[nt][1] };
                float2 v1 = { acc[nt][2], acc[nt][3] };
                *(float2*)(O + r0 + j) = v0;
                *(float2*)(O + r1 + j) = v1;
            }
        }

        // ---- state update: st = gamma*st + (wV)^T K ----
        {
            const float gamma = __expf(lendI - baseL);
            #pragma unroll
            for (int nt = 0; nt < 16; nt++) {
                st[nt][0] *= gamma; st[nt][1] *= gamma;
                st[nt][2] *= gamma; st[nt][3] *= gamma;
            }
        }
        #pragma unroll
        for (int k0 = 0; k0 < CI; k0 += 8) {
            const int r0 = (k0 + q) * SV4, r4 = (k0 + 4 + q) * SV4;
            const int s0 = (k0 + q) * SD4, s4 = (k0 + 4 + q) * SD4;
            const float w0 = wv[k0 + q], w1 = wv[k0 + 4 + q];
            uint32_t af[4];
            af[0] = __float_as_uint(to_tf32(Vs[r0 + jm0 + g] * w0));
            af[1] = __float_as_uint(to_tf32(Vs[r0 + jm0 + 8 + g] * w0));
            af[2] = __float_as_uint(to_tf32(Vs[r4 + jm0 + g] * w1));
            af[3] = __float_as_uint(to_tf32(Vs[r4 + jm0 + 8 + g] * w1));
            #pragma unroll
            for (int nt = 0; nt < 16; nt++) {
                int d0 = nb0 + nt * 8 + g;
                uint32_t bf[2] = { __float_as_uint(Ks[s0 + d0]),
                                   __float_as_uint(Ks[s4 + d0]) };
                mma_tf32(st[nt], af, bf);
            }
        }
        __syncthreads();                                    // S3 (Hs reads done)
        #pragma unroll
        for (int nt = 0; nt < 16; nt++) {
            int d0 = nb0 + nt * 8 + 2 * q;
            float2 h0 = { to_tf32(st[nt][0]), to_tf32(st[nt][1]) };
            float2 h1 = { to_tf32(st[nt][2]), to_tf32(st[nt][3]) };
            *(float2*)(Hs + (jm0 + g) * SD4 + d0)     = h0;
            *(float2*)(Hs + (jm0 + 8 + g) * SD4 + d0) = h1;
        }
    }
}

// ---------------------------------------------------------------------------
extern "C" void kernel_launch(void* const* d_in, const int* in_sizes, int n_in,
                              void* d_out, int out_size)
{
    const float* q    = (const float*)d_in[0];
    const float* k    = (const float*)d_in[1];
    const float* v    = (const float*)d_in[2];
    const float* beta = (const float*)d_in[3];
    float* out = (float*)d_out;
    (void)in_sizes; (void)n_in; (void)out_size;

    cudaFuncSetAttribute(dr_state, cudaFuncAttributeMaxDynamicSharedMemorySize, A_SMEM);
    cudaFuncSetAttribute(dr_out,   cudaFuncAttributeMaxDynamicSharedMemorySize, O_SMEM);

    dr_state<<<dim3(NBG, 2), 512, A_SMEM>>>(k, v, beta);
    dr_scan<<<dim3(64, BB), 256>>>();
    dr_out<<<dim3(NBG, 2), 512, O_SMEM>>>(q, k, v, out);
}

// round 9
// speedup vs baseline: 1.9114x; 1.1490x over previous
#include <cuda_runtime.h>
#include <cstdint>
#include <cstddef>

#define BB 8
#define SS 4096
#define DD 256
#define GG 512      // big chunk
#define NG 8        // big chunks per batch
#define NBG 64      // total big chunks
#define CI 32       // inner chunk
#define NIC 16      // inner chunks per big chunk

// Scratch: per-big-chunk state^T [bg][j][d]; LB converts in place to the
// state ENTERING each big chunk (16.8 MB).
__device__ float g_S[(size_t)NBG * DD * DD];
__device__ float g_Lg[NBG * GG];
__device__ float g_Gamma[NBG];

// ---------------------------------------------------------------------------
// Helpers
// ---------------------------------------------------------------------------
__device__ __forceinline__ uint32_t smem_u32(const void* p) {
    uint32_t a;
    asm("{ .reg .u64 t; cvta.to.shared.u64 t, %1; cvt.u32.u64 %0, t; }"
        : "=r"(a) : "l"(p));
    return a;
}

__device__ __forceinline__ float to_tf32(float f) {
    uint32_t r;
    asm("cvt.rna.tf32.f32 %0, %1;" : "=r"(r) : "f"(f));
    return __uint_as_float(r);
}

__device__ __forceinline__ void mma_tf32(float c[4], const uint32_t a[4],
                                         const uint32_t b[2]) {
    asm volatile(
        "mma.sync.aligned.m16n8k8.row.col.f32.tf32.tf32.f32 "
        "{%0,%1,%2,%3}, {%4,%5,%6,%7}, {%8,%9}, {%0,%1,%2,%3};"
        : "+f"(c[0]), "+f"(c[1]), "+f"(c[2]), "+f"(c[3])
        : "r"(a[0]), "r"(a[1]), "r"(a[2]), "r"(a[3]), "r"(b[0]), "r"(b[1]));
}

__device__ __forceinline__ void ldmx4(uint32_t r[4], uint32_t a) {
    asm volatile("ldmatrix.sync.aligned.m8n8.x4.shared.b16 {%0,%1,%2,%3}, [%4];"
                 : "=r"(r[0]), "=r"(r[1]), "=r"(r[2]), "=r"(r[3]) : "r"(a));
}
__device__ __forceinline__ void ldmx2(uint32_t r[2], uint32_t a) {
    asm volatile("ldmatrix.sync.aligned.m8n8.x2.shared.b16 {%0,%1}, [%2];"
                 : "=r"(r[0]), "=r"(r[1]) : "r"(a));
}

__device__ __forceinline__ void cp16(uint32_t dst, const void* src) {
    asm volatile("cp.async.cg.shared.global [%0], [%1], 16;"
                 :: "r"(dst), "l"(src));
}
#define CP_COMMIT() asm volatile("cp.async.commit_group;" ::: "memory")
#define CP_WAIT0()  asm volatile("cp.async.wait_group 0;" ::: "memory")

// fp32 smem strides (words), ≡ 4 (mod 32): conflict-free b16-trick ldmatrix
#define SD4 260   // 256-wide rows
#define SV4 132   // 128-wide rows
#define SA4 36    // 32-wide rows

// RZ-truncation bias compensation (HMMA truncates fp32 operands to tf32):
// mean relative shrink per RZ operand ~ ln2 * 2^-11 = 3.38e-4.
#define CF1X 1.000338f   // one RZ operand in the product
#define CF2X 1.000677f   // two
#define CF3X 1.001015f   // three

// ---------------------------------------------------------------------------
// LA: big-chunk state contribution T^T[j][d] per (bg, j-half). 512 threads.
//   T[j][d] = sum_{tau<512} (w_tau V[tau][j]) * K[tau][d]
// cp.async double-buffered raw panels; w*V built RNA in regs; K raw (RZ,
// compensated in wv).
// ---------------------------------------------------------------------------
#define A_LGG 0
#define A_WV  2048
#define A_K0  4096
#define A_K1  (A_K0 + 64 * SD4 * 4)    // +66560 -> 70656
#define A_V0  (A_K1 + 64 * SD4 * 4)    // 137216
#define A_V1  (A_V0 + 64 * SV4 * 4)    // 171008
#define A_SMEM (A_V1 + 64 * SV4 * 4)   // 204800

__global__ __launch_bounds__(512, 1) void dr_state(
    const float* __restrict__ K, const float* __restrict__ V,
    const float* __restrict__ beta)
{
    extern __shared__ char sm[];
    float* Lgg = (float*)(sm + A_LGG);
    float* wv  = (float*)(sm + A_WV);
    const uint32_t sb = smem_u32(sm);
    const int bg = blockIdx.x, qj = blockIdx.y;
    const int b = bg >> 3, g2 = bg & 7;
    const int tid = threadIdx.x, wid = tid >> 5, lane = tid & 31;
    const int q = lane & 3, g = lane >> 2;

    const size_t tok0 = (size_t)b * SS + (size_t)g2 * GG;
    const float* Kg = K + tok0 * DD;
    const float* Vg = V + tok0 * DD + qj * 128;

    // issue panel 0
    {
        uint32_t kd = sb + A_K0, vd = sb + A_V0;
        #pragma unroll
        for (int it = 0; it < 8; it++) {
            int idx = it * 512 + tid, row = idx >> 6, c4 = (idx & 63) << 2;
            cp16(kd + (uint32_t)(row * SD4 + c4) * 4, Kg + (size_t)row * DD + c4);
        }
        #pragma unroll
        for (int it = 0; it < 4; it++) {
            int idx = it * 512 + tid, row = idx >> 5, c4 = (idx & 31) << 2;
            cp16(vd + (uint32_t)(row * SV4 + c4) * 4, Vg + (size_t)row * DD + c4);
        }
        CP_COMMIT();
    }

    // cumulative log(beta)
    Lgg[tid] = __logf(fmaxf(beta[tok0 + tid], 1e-30f));
    __syncthreads();
    if (wid == 0) {
        int b0 = lane * 16;
        float s = 0.f;
        #pragma unroll
        for (int u = 0; u < 16; u++) { s += Lgg[b0 + u]; Lgg[b0 + u] = s; }
        float t = s;
        #pragma unroll
        for (int d = 1; d < 32; d <<= 1) {
            float o = __shfl_up_sync(0xFFFFFFFFu, t, d);
            if (lane >= d) t += o;
        }
        float excl = t - s;
        #pragma unroll
        for (int u = 0; u < 16; u++) Lgg[b0 + u] += excl;
    }
    __syncthreads();
    const float lend = Lgg[GG - 1];
    wv[tid] = __expf(lend - Lgg[tid]) * CF1X;   // compensates K-side RZ
    if (qj == 0) {
        g_Lg[bg * GG + tid] = Lgg[tid];
        if (tid == 0) g_Gamma[bg] = __expf(lend);
    }

    const int jm0 = (wid >> 2) * 32;   // 4 j-tiles of 32
    const int i0w = (wid & 3) * 64;    // 4 d-tiles of 64

    float acc[2][8][4];
    #pragma unroll
    for (int mt = 0; mt < 2; mt++)
        #pragma unroll
        for (int nt = 0; nt < 8; nt++)
            #pragma unroll
            for (int u = 0; u < 4; u++) acc[mt][nt][u] = 0.f;

    for (int p = 0; p < 8; p++) {
        CP_WAIT0();
        __syncthreads();
        if (p < 7) {
            uint32_t kd = sb + (((p + 1) & 1) ? A_K1 : A_K0);
            uint32_t vd = sb + (((p + 1) & 1) ? A_V1 : A_V0);
            const float* Kn = Kg + (size_t)(p + 1) * 64 * DD;
            const float* Vn = Vg + (size_t)(p + 1) * 64 * DD;
            #pragma unroll
            for (int it = 0; it < 8; it++) {
                int idx = it * 512 + tid, row = idx >> 6, c4 = (idx & 63) << 2;
                cp16(kd + (uint32_t)(row * SD4 + c4) * 4, Kn + (size_t)row * DD + c4);
            }
            #pragma unroll
            for (int it = 0; it < 4; it++) {
                int idx = it * 512 + tid, row = idx >> 5, c4 = (idx & 31) << 2;
                cp16(vd + (uint32_t)(row * SV4 + c4) * 4, Vn + (size_t)row * DD + c4);
            }
            CP_COMMIT();
        }
        const float* Kp = (const float*)(sm + ((p & 1) ? A_K1 : A_K0));
        const float* Vp = (const float*)(sm + ((p & 1) ? A_V1 : A_V0));
        const float* wp = wv + p * 64;

        #pragma unroll
        for (int k0 = 0; k0 < 64; k0 += 8) {
            const int r0 = (k0 + q) * SV4, r4 = (k0 + 4 + q) * SV4;
            const int s0 = (k0 + q) * SD4, s4 = (k0 + 4 + q) * SD4;
            const float w0 = wp[k0 + q], w1 = wp[k0 + 4 + q];
            uint32_t af[2][4], bf[8][2];
            #pragma unroll
            for (int mt = 0; mt < 2; mt++) {
                int jb = jm0 + mt * 16 + g;
                af[mt][0] = __float_as_uint(to_tf32(Vp[r0 + jb] * w0));
                af[mt][1] = __float_as_uint(to_tf32(Vp[r0 + jb + 8] * w0));
                af[mt][2] = __float_as_uint(to_tf32(Vp[r4 + jb] * w1));
                af[mt][3] = __float_as_uint(to_tf32(Vp[r4 + jb + 8] * w1));
            }
            #pragma unroll
            for (int nt = 0; nt < 8; nt++) {
                int db = i0w + nt * 8 + g;
                bf[nt][0] = __float_as_uint(Kp[s0 + db]);
                bf[nt][1] = __float_as_uint(Kp[s4 + db]);
            }
            #pragma unroll
            for (int mt = 0; mt < 2; mt++)
                #pragma unroll
                for (int nt = 0; nt < 8; nt++)
                    mma_tf32(acc[mt][nt], af[mt], bf[nt]);
        }
    }

    float* Sdst = g_S + (size_t)bg * 65536 + (size_t)(qj * 128) * 256;
    #pragma unroll
    for (int mt = 0; mt < 2; mt++)
        #pragma unroll
        for (int nt = 0; nt < 8; nt++) {
            int j = jm0 + mt * 16 + g;
            int d = i0w + nt * 8 + 2 * q;
            float2 v0 = { acc[mt][nt][0], acc[mt][nt][1] };
            float2 v1 = { acc[mt][nt][2], acc[mt][nt][3] };
            *(float2*)(Sdst + (size_t)j * 256 + d) = v0;
            *(float2*)(Sdst + (size_t)(j + 8) * 256 + d) = v1;
        }
}

// ---------------------------------------------------------------------------
// LB: 8-step scan over big-chunk states (in place -> state entering bg).
// ---------------------------------------------------------------------------
__global__ __launch_bounds__(256) void dr_scan()
{
    const int b = blockIdx.y;
    const size_t e4 = ((size_t)blockIdx.x * 256 + threadIdx.x) * 4;
    float4 h = { 0.f, 0.f, 0.f, 0.f };
    #pragma unroll
    for (int g2 = 0; g2 < NG; g2++) {
        const int bg = b * NG + g2;
        const size_t off = (size_t)bg * 65536 + e4;
        const float gc = g_Gamma[bg];
        float4 s = *(const float4*)(g_S + off);
        *(float4*)(g_S + off) = h;
        h.x = gc * h.x + s.x; h.y = gc * h.y + s.y;
        h.z = gc * h.z + s.z; h.w = gc * h.w + s.w;
    }
}

// ---------------------------------------------------------------------------
// LC: fused per-(bg, j-half) kernel. State H^T[j 128][d 256] ONLY in
// registers (64 fp32/thread, as state-update MMA accumulators). Q@H uses the
// state regs directly as B-fragments via intra-quad shuffles; warp pairs
// (d-halves) reduce partials via smem. cp.async double-buffered Q/K/V.
// ---------------------------------------------------------------------------
#define C_LGG 0
#define C_WV  2048
#define C_SG  2176
#define C_Q0  2304
#define C_Q1  (C_Q0 + 32 * SD4 * 4)    // +33280 -> 35584
#define C_K0  68864
#define C_K1  (C_K0 + 32 * SD4 * 4)    // 102144
#define C_V0  135424
#define C_V1  (C_V0 + 32 * SV4 * 4)    // 152320
#define C_AS  169216                   // 32*36*4 = 4608
#define C_R0  173824                   // 32*132*4 = 16896
#define C_R1  190720
#define C_SMEM 207616

__global__ __launch_bounds__(512, 1) void dr_out(
    const float* __restrict__ Q, const float* __restrict__ K,
    const float* __restrict__ V, float* __restrict__ O)
{
    extern __shared__ char sm[];
    float* Lgg = (float*)(sm + C_LGG);
    float* wv  = (float*)(sm + C_WV);
    float* sg  = (float*)(sm + C_SG);
    float* Asf = (float*)(sm + C_AS);
    float* R0f = (float*)(sm + C_R0);
    float* R1f = (float*)(sm + C_R1);
    const uint32_t sb = smem_u32(sm);

    const int bg = blockIdx.x, jh = blockIdx.y;
    const int b = bg >> 3, g2 = bg & 7;
    const int tid = threadIdx.x, wid = tid >> 5, lane = tid & 31;
    const int q = lane & 3, g = lane >> 2;
    const int rA = lane & 15, cA = (lane >> 4) * 4;
    const int rB = lane & 7,  cB = ((lane >> 3) & 1) * 4;

    const size_t tok0 = (size_t)b * SS + (size_t)g2 * GG;
    const float* Qg = Q + tok0 * DD;
    const float* Kg = K + tok0 * DD;
    const float* Vg = V + tok0 * DD + jh * 128;

    // issue chunk 0
    {
        uint32_t qd = sb + C_Q0, kd = sb + C_K0, vd = sb + C_V0;
        #pragma unroll
        for (int it = 0; it < 4; it++) {
            int idx = it * 512 + tid, row = idx >> 6, c4 = (idx & 63) << 2;
            cp16(qd + (uint32_t)(row * SD4 + c4) * 4, Qg + (size_t)row * DD + c4);
            cp16(kd + (uint32_t)(row * SD4 + c4) * 4, Kg + (size_t)row * DD + c4);
        }
        #pragma unroll
        for (int it = 0; it < 2; it++) {
            int idx = it * 512 + tid, row = idx >> 5, c4 = (idx & 31) << 2;
            cp16(vd + (uint32_t)(row * SV4 + c4) * 4, Vg + (size_t)row * DD + c4);
        }
        CP_COMMIT();
    }

    Lgg[tid] = g_Lg[bg * GG + tid];

    // state regs: warp tile [j 16][d 128]; pairs (2w,2w+1) split d.
    const int jm0 = (wid >> 1) * 16;
    const int nb0 = (wid & 1) * 128;
    float st[16][4];
    {
        const float* Sg = g_S + (size_t)bg * 65536 + (size_t)(jh * 128) * 256;
        #pragma unroll
        for (int nt = 0; nt < 16; nt++) {
            int d = nb0 + nt * 8 + 2 * q;
            float2 lo = *(const float2*)(Sg + (size_t)(jm0 + g) * 256 + d);
            float2 hi = *(const float2*)(Sg + (size_t)(jm0 + 8 + g) * 256 + d);
            st[nt][0] = lo.x; st[nt][1] = lo.y;
            st[nt][2] = hi.x; st[nt][3] = hi.y;
        }
    }

    const int srcq = (lane & ~3) | (q >> 1);
    const uint32_t asb = sb + C_AS;

    for (int ic = 0; ic < NIC; ic++) {
        const int icb = ic * CI;
        CP_WAIT0();
        __syncthreads();                                   // buffers ready/free
        if (ic < NIC - 1) {
            uint32_t qd = sb + (((ic + 1) & 1) ? C_Q1 : C_Q0);
            uint32_t kd = sb + (((ic + 1) & 1) ? C_K1 : C_K0);
            uint32_t vd = sb + (((ic + 1) & 1) ? C_V1 : C_V0);
            const float* Qn = Qg + (size_t)(icb + CI) * DD;
            const float* Kn = Kg + (size_t)(icb + CI) * DD;
            const float* Vn = Vg + (size_t)(icb + CI) * DD;
            #pragma unroll
            for (int it = 0; it < 4; it++) {
                int idx = it * 512 + tid, row = idx >> 6, c4 = (idx & 63) << 2;
                cp16(qd + (uint32_t)(row * SD4 + c4) * 4, Qn + (size_t)row * DD + c4);
                cp16(kd + (uint32_t)(row * SD4 + c4) * 4, Kn + (size_t)row * DD + c4);
            }
            #pragma unroll
            for (int it = 0; it < 2; it++) {
                int idx = it * 512 + tid, row = idx >> 5, c4 = (idx & 31) << 2;
                cp16(vd + (uint32_t)(row * SV4 + c4) * 4, Vn + (size_t)row * DD + c4);
            }
            CP_COMMIT();
        }

        const float baseL = ic ? Lgg[icb - 1] : 0.f;
        const float lendI = Lgg[icb + CI - 1];
        if (tid < CI) {
            float lt = Lgg[icb + tid];
            wv[tid] = __expf(lendI - lt) * CF1X;     // + K-RZ comp
            sg[tid] = __expf(lt - baseL) * CF2X;     // + Q-RZ + st-RZ comp
        }

        const uint32_t qbc = sb + ((ic & 1) ? C_Q1 : C_Q0);
        const uint32_t kbc = sb + ((ic & 1) ? C_K1 : C_K0);
        const float* Vc = (const float*)(sm + ((ic & 1) ? C_V1 : C_V0));
        const float* Kc = (const float*)(sm + ((ic & 1) ? C_K1 : C_K0));

        // ---- Phase 1 (all warps): Q@H partials from state regs ----
        float* Rb = (wid & 1) ? R1f : R0f;
        #pragma unroll
        for (int it = 0; it < 2; it++) {
            float accP[2][4];
            #pragma unroll
            for (int nb = 0; nb < 2; nb++)
                #pragma unroll
                for (int u = 0; u < 4; u++) accP[nb][u] = 0.f;
            #pragma unroll
            for (int nt = 0; nt < 16; nt++) {
                // B-frags from state accumulator frags (intra-quad shuffles)
                float s00 = __shfl_sync(0xFFFFFFFFu, st[nt][0], srcq);
                float s01 = __shfl_sync(0xFFFFFFFFu, st[nt][1], srcq);
                float s02 = __shfl_sync(0xFFFFFFFFu, st[nt][0], srcq + 2);
                float s03 = __shfl_sync(0xFFFFFFFFu, st[nt][1], srcq + 2);
                float s10 = __shfl_sync(0xFFFFFFFFu, st[nt][2], srcq);
                float s11 = __shfl_sync(0xFFFFFFFFu, st[nt][3], srcq);
                float s12 = __shfl_sync(0xFFFFFFFFu, st[nt][2], srcq + 2);
                float s13 = __shfl_sync(0xFFFFFFFFu, st[nt][3], srcq + 2);
                uint32_t blo[2] = { __float_as_uint((q & 1) ? s01 : s00),
                                    __float_as_uint((q & 1) ? s03 : s02) };
                uint32_t bhi[2] = { __float_as_uint((q & 1) ? s11 : s10),
                                    __float_as_uint((q & 1) ? s13 : s12) };
                uint32_t af[4];
                ldmx4(af, qbc + (uint32_t)((it * 16 + rA) * SD4 + nb0 + nt * 8 + cA) * 4);
                mma_tf32(accP[0], af, blo);
                mma_tf32(accP[1], af, bhi);
            }
            #pragma unroll
            for (int nb = 0; nb < 2; nb++) {
                int jc = jm0 + nb * 8 + 2 * q;
                *(float2*)(Rb + (it * 16 + g) * SV4 + jc) =
                    make_float2(accP[nb][0], accP[nb][1]);
                *(float2*)(Rb + (it * 16 + 8 + g) * SV4 + jc) =
                    make_float2(accP[nb][2], accP[nb][3]);
            }
        }
        __syncthreads();                                   // partials + wv/sg visible

        if (!(wid & 1)) {
            // ---- even warps: QK^T -> masked decayed A ----
            int e = wid >> 1;
            int i0q = (e >> 2) * 16, t0q = (e & 3) * 8;
            float a1[4] = { 0.f, 0.f, 0.f, 0.f };
            #pragma unroll
            for (int k0 = 0; k0 < 256; k0 += 8) {
                uint32_t af[4], bf[2];
                ldmx4(af, qbc + (uint32_t)((i0q + rA) * SD4 + k0 + cA) * 4);
                ldmx2(bf, kbc + (uint32_t)((t0q + rB) * SD4 + k0 + cB) * 4);
                mma_tf32(a1, af, bf);
            }
            int ia = i0q + g, ib2 = ia + 8, t = t0q + 2 * q;
            float lia = Lgg[icb + ia], lib = Lgg[icb + ib2];
            float lt0 = Lgg[icb + t], lt1 = Lgg[icb + t + 1];
            float f00 = (t     <= ia)  ? __expf(lia - lt0) * CF3X : 0.f;
            float f01 = (t + 1 <= ia)  ? __expf(lia - lt1) * CF3X : 0.f;
            float f10 = (t     <= ib2) ? __expf(lib - lt0) * CF3X : 0.f;
            float f11 = (t + 1 <= ib2) ? __expf(lib - lt1) * CF3X : 0.f;
            *(float2*)(Asf + ia * SA4 + t) =
                make_float2(to_tf32(a1[0] * f00), to_tf32(a1[1] * f01));
            *(float2*)(Asf + ib2 * SA4 + t) =
                make_float2(to_tf32(a1[2] * f10), to_tf32(a1[3] * f11));
        } else {
            // ---- odd warps: state update ----
            const float gamma = __expf(lendI - baseL);
            #pragma unroll
            for (int nt = 0; nt < 16; nt++) {
                st[nt][0] *= gamma; st[nt][1] *= gamma;
                st[nt][2] *= gamma; st[nt][3] *= gamma;
            }
            #pragma unroll
            for (int k0 = 0; k0 < CI; k0 += 8) {
                const int r0 = (k0 + q) * SV4, r4 = (k0 + 4 + q) * SV4;
                const int s0 = (k0 + q) * SD4, s4 = (k0 + 4 + q) * SD4;
                const float w0 = wv[k0 + q], w1 = wv[k0 + 4 + q];
                uint32_t af[4];
                af[0] = __float_as_uint(to_tf32(Vc[r0 + jm0 + g] * w0));
                af[1] = __float_as_uint(to_tf32(Vc[r0 + jm0 + 8 + g] * w0));
                af[2] = __float_as_uint(to_tf32(Vc[r4 + jm0 + g] * w1));
                af[3] = __float_as_uint(to_tf32(Vc[r4 + jm0 + 8 + g] * w1));
                #pragma unroll
                for (int nt = 0; nt < 16; nt++) {
                    int d0 = nb0 + nt * 8 + g;
                    uint32_t bf[2] = { __float_as_uint(Kc[s0 + d0]),
                                       __float_as_uint(Kc[s4 + d0]) };
                    mma_tf32(st[nt], af, bf);
                }
            }
        }
        __syncthreads();                                   // As visible

        if (wid & 1) {
            // ---- odd warps: combine partials, A@V, store O ----
            #pragma unroll
            for (int it = 0; it < 2; it++) {
                float sa = sg[it * 16 + g], sb2 = sg[it * 16 + 8 + g];
                float acc[2][4];
                #pragma unroll
                for (int nb = 0; nb < 2; nb++) {
                    int jc = jm0 + nb * 8 + 2 * q;
                    float2 a0 = *(float2*)(R1f + (it * 16 + g) * SV4 + jc);
                    float2 b0 = *(float2*)(R0f + (it * 16 + g) * SV4 + jc);
                    float2 a1 = *(float2*)(R1f + (it * 16 + 8 + g) * SV4 + jc);
                    float2 b1 = *(float2*)(R0f + (it * 16 + 8 + g) * SV4 + jc);
                    acc[nb][0] = sa * (a0.x + b0.x);
                    acc[nb][1] = sa * (a0.y + b0.y);
                    acc[nb][2] = sb2 * (a1.x + b1.x);
                    acc[nb][3] = sb2 * (a1.y + b1.y);
                }
                #pragma unroll
                for (int k0 = 0; k0 < CI; k0 += 8) {
                    uint32_t af[4];
                    ldmx4(af, asb + (uint32_t)((it * 16 + rA) * SA4 + k0 + cA) * 4);
                    #pragma unroll
                    for (int nb = 0; nb < 2; nb++) {
                        int jc = jm0 + nb * 8 + g;
                        uint32_t bf[2] = {
                            __float_as_uint(Vc[(k0 + q) * SV4 + jc]),
                            __float_as_uint(Vc[(k0 + 4 + q) * SV4 + jc]) };
                        mma_tf32(acc[nb], af, bf);
                    }
                }
                size_t ro0 = (tok0 + icb + it * 16 + g) * DD + jh * 128;
                size_t ro1 = (tok0 + icb + it * 16 + 8 + g) * DD + jh * 128;
                #pragma unroll
                for (int nb = 0; nb < 2; nb++) {
                    int jc = jm0 + nb * 8 + 2 * q;
                    *(float2*)(O + ro0 + jc) = make_float2(acc[nb][0], acc[nb][1]);
                    *(float2*)(O + ro1 + jc) = make_float2(acc[nb][2], acc[nb][3]);
                }
            }
        } else {
            // ---- even warps: state update ----
            const float gamma = __expf(lendI - baseL);
            #pragma unroll
            for (int nt = 0; nt < 16; nt++) {
                st[nt][0] *= gamma; st[nt][1] *= gamma;
                st[nt][2] *= gamma; st[nt][3] *= gamma;
            }
            #pragma unroll
            for (int k0 = 0; k0 < CI; k0 += 8) {
                const int r0 = (k0 + q) * SV4, r4 = (k0 + 4 + q) * SV4;
                const int s0 = (k0 + q) * SD4, s4 = (k0 + 4 + q) * SD4;
                const float w0 = wv[k0 + q], w1 = wv[k0 + 4 + q];
                uint32_t af[4];
                af[0] = __float_as_uint(to_tf32(Vc[r0 + jm0 + g] * w0));
                af[1] = __float_as_uint(to_tf32(Vc[r0 + jm0 + 8 + g] * w0));
                af[2] = __float_as_uint(to_tf32(Vc[r4 + jm0 + g] * w1));
                af[3] = __float_as_uint(to_tf32(Vc[r4 + jm0 + 8 + g] * w1));
                #pragma unroll
                for (int nt = 0; nt < 16; nt++) {
                    int d0 = nb0 + nt * 8 + g;
                    uint32_t bf[2] = { __float_as_uint(Kc[s0 + d0]),
                                       __float_as_uint(Kc[s4 + d0]) };
                    mma_tf32(st[nt], af, bf);
                }
            }
        }
    }
}

// ---------------------------------------------------------------------------
extern "C" void kernel_launch(void* const* d_in, const int* in_sizes, int n_in,
                              void* d_out, int out_size)
{
    const float* q    = (const float*)d_in[0];
    const float* k    = (const float*)d_in[1];
    const float* v    = (const float*)d_in[2];
    const float* beta = (const float*)d_in[3];
    float* out = (float*)d_out;
    (void)in_sizes; (void)n_in; (void)out_size;

    cudaFuncSetAttribute(dr_state, cudaFuncAttributeMaxDynamicSharedMemorySize, A_SMEM);
    cudaFuncSetAttribute(dr_out,   cudaFuncAttributeMaxDynamicSharedMemorySize, C_SMEM);

    dr_state<<<dim3(NBG, 2), 512, A_SMEM>>>(k, v, beta);
    dr_scan<<<dim3(64, BB), 256>>>();
    dr_out<<<dim3(NBG, 2), 512, C_SMEM>>>(q, k, v, out);
}